// round 5
// baseline (speedup 1.0000x reference)
#include <cuda_runtime.h>

#define BETA   0.9f
#define NT     32                 // time steps
#define TCH    8                  // time chunk
#define NCHUNK (NT / TCH)
#define TILE_Q 255                // pooled (q) positions per CTA
#define NTILE  9                  // ceil(2048/255)
#define NTHR   512
#define PSTR   520                // padded row stride for spike bytes
#define XCNT   1026               // x window floats needed

// [b][tile][t][o] partial FC sums
__device__ float g_partial[256 * NTILE * NT * 2];

__device__ __forceinline__ float4 add4(float4 a, float4 b) {
    return make_float4(a.x + b.x, a.y + b.y, a.z + b.z, a.w + b.w);
}
__device__ __forceinline__ float4 max4(float4 a, float4 b) {
    return make_float4(fmaxf(a.x, b.x), fmaxf(a.y, b.y),
                       fmaxf(a.z, b.z), fmaxf(a.w, b.w));
}

__global__ __launch_bounds__(NTHR, 3) void snn_main(
    const float* __restrict__ x,     // [256,1,8192]
    const float* __restrict__ w1,    // [8,1,3]
    const float* __restrict__ b1,    // [8]
    const float* __restrict__ w2,    // [8,8,3]
    const float* __restrict__ b2,    // [8]
    const float* __restrict__ fcw,   // [2,16384]
    const float* __restrict__ th1p,
    const float* __restrict__ th2p)
{
    __shared__ __align__(16) float lut[3 * 256 * 8];   // 24576 B
    __shared__ unsigned char sb[TCH][PSTR];            // 4160 B
    __shared__ float sx[XCNT + 2];                     // 4112 B
    __shared__ float psum[NT][16][2][2];               // 8192 B
    __shared__ float sw1[24], sbias1[8];

    const int blk  = blockIdx.x;
    const int b    = blk / NTILE;
    const int tile = blk - b * NTILE;
    const int tid  = threadIdx.x;
    const int q0   = tile * TILE_Q;
    const float th1 = *th1p;
    const float th2 = *th2p;

    if (tid < 24) sw1[tid] = w1[tid];
    if (tid < 8)  sbias1[tid] = b1[tid];

    // ---- Build conv2 byte-LUT: lut[(k*256+s)*8+co] = sum_{ci in s} w2[co][ci][k]
    // (conv2 bias folded into tap-1 LUT; exactly one tap-1 term per position)
    for (int idx = tid; idx < 3 * 256; idx += NTHR) {
        const int k = idx >> 8;
        const int s = idx & 255;
        float acc[8];
        #pragma unroll
        for (int co = 0; co < 8; co++) acc[co] = (k == 1) ? b2[co] : 0.f;
        #pragma unroll
        for (int ci = 0; ci < 8; ci++) {
            if ((s >> ci) & 1) {
                #pragma unroll
                for (int co = 0; co < 8; co++)
                    acc[co] += w2[(co * 8 + ci) * 3 + k];
            }
        }
        float4* row = reinterpret_cast<float4*>(lut + idx * 8);
        row[0] = make_float4(acc[0], acc[1], acc[2], acc[3]);
        row[1] = make_float4(acc[4], acc[5], acc[6], acc[7]);
    }

    // ---- Load the x window this tile needs (zero-padded at edges)
    const int xbase = 4 * q0 - 3;
    const float* xb = x + b * 8192;
    for (int i = tid; i < XCNT; i += NTHR) {
        const int xg = xbase + i;
        sx[i] = (xg >= 0 && xg < 8192) ? xb[xg] : 0.f;
    }

    // ---- Layer-1 persistent state: one spk1 position per thread
    const int lg = (2 * q0 - 1) + tid;            // global spk1 position
    const bool pvalid = (lg >= 0 && lg < 4096);
    float m1[8];
    #pragma unroll
    for (int c = 0; c < 8; c++) m1[c] = 0.f;
    unsigned sp1 = 0;

    // ---- conv2/FC thread role: q = tid>>1, h = tid&1 (co 4h..4h+3, o = h)
    const int qloc = tid >> 1;
    const int h    = tid & 1;
    const int qg   = q0 + qloc;
    const bool qvalid = (qloc < TILE_Q) && (qg < 2048);
    const float* lutT = lut + 4 * h;

    float fw[8], m2[4];
    #pragma unroll
    for (int co = 0; co < 8; co++)
        fw[co] = qvalid ? fcw[h * 16384 + co * 2048 + qg] : 0.f;
    #pragma unroll
    for (int j = 0; j < 4; j++) m2[j] = 0.f;

    const int lane = tid & 31, wrp = tid >> 5;
    const int p = 2 * qloc;
    __syncthreads();

    // ==== Chunked time loop ====
    #pragma unroll 1
    for (int ch = 0; ch < NCHUNK; ch++) {
        // -- recompute layer-1 constant current (cheap, saves 8 regs)
        float cur[8];
        {
            const float x0 = sx[2 * tid],     x1 = sx[2 * tid + 1];
            const float x2 = sx[2 * tid + 2], x3 = sx[2 * tid + 3];
            #pragma unroll
            for (int c = 0; c < 8; c++) {
                const float wa = sw1[3 * c], wb = sw1[3 * c + 1], wc = sw1[3 * c + 2];
                const float y0 = wa * x0 + wb * x1 + wc * x2;
                const float y1 = wa * x1 + wb * x2 + wc * x3;
                cur[c] = fmaxf(y0, y1) + sbias1[c];
            }
        }
        // -- produce TCH rows of layer-1 spike bytes
        #pragma unroll
        for (int tt = 0; tt < TCH; tt++) {
            unsigned byte = 0;
            if (pvalid) {
                #pragma unroll
                for (int c = 0; c < 8; c++) {
                    float mm = BETA * m1[c] + cur[c];
                    if ((sp1 >> c) & 1) mm -= th1;
                    m1[c] = mm;
                    if (mm > th1) byte |= (1u << c);
                }
                sp1 = byte;
            }
            sb[tt][tid] = (unsigned char)byte;
        }
        __syncthreads();

        // -- consume: conv2(LUT) + pool + LIF2 + FC partial
        #pragma unroll 1
        for (int tt = 0; tt < TCH; tt++) {
            const unsigned char* row = sb[tt];
            const unsigned s0 = row[p], s1 = row[p + 1];
            const unsigned s2 = row[p + 2], s3 = row[p + 3];

            const float4 A0 = *reinterpret_cast<const float4*>(lutT + (0 * 256 + (int)s0) * 8);
            const float4 A1 = *reinterpret_cast<const float4*>(lutT + (1 * 256 + (int)s1) * 8);
            const float4 A2 = *reinterpret_cast<const float4*>(lutT + (2 * 256 + (int)s2) * 8);
            const float4 B0 = *reinterpret_cast<const float4*>(lutT + (0 * 256 + (int)s1) * 8);
            const float4 B1 = *reinterpret_cast<const float4*>(lutT + (1 * 256 + (int)s2) * 8);
            const float4 B2 = *reinterpret_cast<const float4*>(lutT + (2 * 256 + (int)s3) * 8);

            const float4 cv = max4(add4(add4(A0, A1), A2), add4(add4(B0, B1), B2));
            const float cur2[4] = {cv.x, cv.y, cv.z, cv.w};

            unsigned nib = 0;
            #pragma unroll
            for (int j = 0; j < 4; j++) {
                float mm = m2[j];
                const bool r = mm > th2;          // reset from carry-in mem
                mm = BETA * mm + cur2[j];
                if (r) mm -= th2;
                m2[j] = mm;
                if (mm > th2) nib |= (1u << j);
            }
            // full 8-co spike mask for this q: own half | partner half
            const unsigned own  = nib << (4 * h);
            const unsigned full = own | __shfl_xor_sync(0xffffffffu, own, 1);

            float pacc = 0.f;
            #pragma unroll
            for (int co = 0; co < 8; co++)
                if ((full >> co) & 1) pacc += fw[co];

            // truncated xor-butterfly (offs 2,4,8): lane l sums its parity's
            // 8 lanes within the 16-lane half-warp
            pacc += __shfl_xor_sync(0xffffffffu, pacc, 2);
            pacc += __shfl_xor_sync(0xffffffffu, pacc, 4);
            pacc += __shfl_xor_sync(0xffffffffu, pacc, 8);

            if ((lane & 15) < 2)
                psum[ch * TCH + tt][wrp][lane >> 4][lane & 1] = pacc;
        }
        __syncthreads();
    }

    // ---- Epilogue: reduce psum over 16 warps x 2 groups
    if (tid < 64) {
        const int t = tid >> 1, o = tid & 1;
        float s = 0.f;
        #pragma unroll
        for (int w = 0; w < 16; w++)
            s += psum[t][w][0][o] + psum[t][w][1][o];
        g_partial[((b * NTILE + tile) * NT + t) * 2 + o] = s;
    }
}

__global__ __launch_bounds__(64) void snn_final(
    const float* __restrict__ fcb,
    const float* __restrict__ thop,
    float* __restrict__ out)
{
    __shared__ float sm[NT][2];
    const int b = blockIdx.x;
    const int tid = threadIdx.x;

    {
        const int t = tid >> 1, o = tid & 1;
        float s = 0.f;
        #pragma unroll
        for (int tile = 0; tile < NTILE; tile++)
            s += g_partial[((b * NTILE + tile) * NT + t) * 2 + o];
        sm[t][o] = s;
    }
    __syncthreads();

    if (tid < 2) {
        const int o = tid;
        const float tho = *thop;
        const float fb = fcb[o];
        float mo = 0.f;
        for (int t = 0; t < NT; t++) {
            const float c = sm[t][o] + fb;
            const bool r = mo > tho;
            mo = BETA * mo + c;
            if (r) mo -= tho;
            const int base = (t * 256 + b) * 2 + o;
            out[base] = (mo > tho) ? 1.f : 0.f;   // spk_rec
            out[16384 + base] = mo;               // mem_rec
        }
    }
}

extern "C" void kernel_launch(void* const* d_in, const int* in_sizes, int n_in,
                              void* d_out, int out_size)
{
    const float* x    = (const float*)d_in[0];
    const float* w1   = (const float*)d_in[1];
    const float* b1   = (const float*)d_in[2];
    const float* w2   = (const float*)d_in[3];
    const float* b2   = (const float*)d_in[4];
    const float* fcw  = (const float*)d_in[5];
    const float* fcb  = (const float*)d_in[6];
    const float* th1  = (const float*)d_in[7];
    const float* th2  = (const float*)d_in[8];
    const float* tho  = (const float*)d_in[9];
    float* out = (float*)d_out;

    snn_main<<<256 * NTILE, NTHR>>>(x, w1, b1, w2, b2, fcw, th1, th2);
    snn_final<<<256, 64>>>(fcb, tho, out);
}

// round 6
// speedup vs baseline: 1.2562x; 1.2562x over previous
#include <cuda_runtime.h>

#define BETA   0.9f
#define NT     32                 // time steps
#define TCH    8                  // time chunk
#define NCHUNK (NT / TCH)
#define TILE_Q 256                // pooled (q) positions per CTA
#define NTILE  8
#define NTHR   512
#define NP     514                // spk1 positions incl. halo
#define PSTR   520                // padded row stride for spike bytes (4-aligned)
#define XCNT   1030               // x window floats needed

// dynamic smem layout (bytes)
#define LUT_BYTES (3 * 256 * 4 * 8 * 4)        // 98304: lutR[3][256][4 copies][8 co]
#define SB_OFF    LUT_BYTES                     // spike bytes [TCH][PSTR] = 4160
#define PS_OFF    (SB_OFF + TCH * PSTR)         // psum region (8192 B); sx aliases it
#define SMEM_TOTAL (PS_OFF + NT * 16 * 2 * 2 * 4)   // 110656

// [b][tile][t][o] partial FC sums
__device__ float g_partial[256 * NTILE * NT * 2];

__device__ __forceinline__ float4 add4(float4 a, float4 b) {
    return make_float4(a.x + b.x, a.y + b.y, a.z + b.z, a.w + b.w);
}
__device__ __forceinline__ float4 max4(float4 a, float4 b) {
    return make_float4(fmaxf(a.x, b.x), fmaxf(a.y, b.y),
                       fmaxf(a.z, b.z), fmaxf(a.w, b.w));
}

__global__ __launch_bounds__(NTHR, 2) void snn_main(
    const float* __restrict__ x,     // [256,1,8192]
    const float* __restrict__ w1,    // [8,1,3]
    const float* __restrict__ b1,    // [8]
    const float* __restrict__ w2,    // [8,8,3]
    const float* __restrict__ b2,    // [8]
    const float* __restrict__ fcw,   // [2,16384]
    const float* __restrict__ th1p,
    const float* __restrict__ th2p)
{
    extern __shared__ __align__(16) unsigned char smem[];
    float*         lutR = reinterpret_cast<float*>(smem);          // [3][256][4][8]
    unsigned char* sb   = smem + SB_OFF;                           // [TCH][PSTR]
    float*         sx   = reinterpret_cast<float*>(smem + PS_OFF); // [XCNT] (init only)
    float (*psum)[16][2][2] = reinterpret_cast<float (*)[16][2][2]>(smem + PS_OFF);

    __shared__ float halo_m[2][8];     // layer-1 state for positions 512,513
    __shared__ float halo_cur[2][8];
    __shared__ unsigned halo_sp[2];

    const int blk  = blockIdx.x;
    const int b    = blk >> 3;
    const int tile = blk & 7;
    const int tid  = threadIdx.x;
    const int q0   = tile * TILE_Q;
    const float th1 = *th1p;
    const float th2 = *th2p;

    // ---- Build conv2 byte-LUTs, replicated 4x (provably conflict-free):
    // lutR[k][s][j][co] = sum_{ci in s} w2[co][ci][k]  (+ bias folded into k=1)
    for (int idx = tid; idx < 3 * 256; idx += NTHR) {
        const int k = idx >> 8;
        const int s = idx & 255;
        float acc[8];
        #pragma unroll
        for (int co = 0; co < 8; co++) acc[co] = (k == 1) ? b2[co] : 0.f;
        #pragma unroll
        for (int ci = 0; ci < 8; ci++) {
            if ((s >> ci) & 1) {
                #pragma unroll
                for (int co = 0; co < 8; co++)
                    acc[co] += w2[(co * 8 + ci) * 3 + k];
            }
        }
        float4* row = reinterpret_cast<float4*>(lutR + idx * 32);
        const float4 lo = make_float4(acc[0], acc[1], acc[2], acc[3]);
        const float4 hi = make_float4(acc[4], acc[5], acc[6], acc[7]);
        #pragma unroll
        for (int j = 0; j < 4; j++) { row[2 * j] = lo; row[2 * j + 1] = hi; }
    }

    // ---- Load the x window this tile needs (zero-padded at edges)
    const int xbase = 4 * q0 - 3;
    const float* xb = x + b * 8192;
    for (int i = tid; i < XCNT; i += NTHR) {
        const int xg = xbase + i;
        sx[i] = (xg >= 0 && xg < 8192) ? xb[xg] : 0.f;
    }
    __syncthreads();

    // ---- Layer-1 state: position tid (registers); positions 512/513 in SMEM
    const int lg = (2 * q0 - 1) + tid;
    const bool pvalid = (lg >= 0 && lg < 4096);
    float cur[8], m1[8];
    {
        const float x0 = sx[2 * tid],     x1 = sx[2 * tid + 1];
        const float x2 = sx[2 * tid + 2], x3 = sx[2 * tid + 3];
        #pragma unroll
        for (int c = 0; c < 8; c++) {
            const float wa = w1[3 * c], wb = w1[3 * c + 1], wc = w1[3 * c + 2];
            const float y0 = wa * x0 + wb * x1 + wc * x2;
            const float y1 = wa * x1 + wb * x2 + wc * x3;
            cur[c] = fmaxf(y0, y1) + b1[c];
            m1[c] = 0.f;
        }
    }
    unsigned sp1 = 0;
    if (tid < 2) {
        const int ll = 512 + tid;
        const float x0 = sx[2 * ll],     x1 = sx[2 * ll + 1];
        const float x2 = sx[2 * ll + 2], x3 = sx[2 * ll + 3];
        #pragma unroll
        for (int c = 0; c < 8; c++) {
            const float wa = w1[3 * c], wb = w1[3 * c + 1], wc = w1[3 * c + 2];
            const float y0 = wa * x0 + wb * x1 + wc * x2;
            const float y1 = wa * x1 + wb * x2 + wc * x3;
            halo_cur[tid][c] = fmaxf(y0, y1) + b1[c];
            halo_m[tid][c] = 0.f;
        }
        halo_sp[tid] = 0;
    }

    // ---- conv2/FC role: q = tid>>1, h = tid&1 (co 4h..4h+3, output o = h),
    // LUT copy j = q&3 -> every 8-lane LDS.128 phase hits 8 distinct 16B slots.
    const int qloc = tid >> 1;
    const int h    = tid & 1;
    const int qg   = q0 + qloc;
    const float* lutT = lutR + (qloc & 3) * 8 + 4 * h;

    float fw[8], m2[4];
    #pragma unroll
    for (int co = 0; co < 8; co++)
        fw[co] = fcw[h * 16384 + co * 2048 + qg];
    #pragma unroll
    for (int j = 0; j < 4; j++) m2[j] = 0.f;

    const int lane = tid & 31, wrp = tid >> 5;
    const int p      = 2 * qloc;
    const int wbase  = p & ~3;            // aligned word offset
    const int fsh    = (p & 3) * 8;       // funnel shift (0 or 16)
    __syncthreads();   // sx fully consumed before psum aliasing writes

    // ==== Chunked time loop ====
    #pragma unroll 1
    for (int ch = 0; ch < NCHUNK; ch++) {
        // -- produce TCH rows of layer-1 spike bytes
        #pragma unroll
        for (int tt = 0; tt < TCH; tt++) {
            unsigned byte = 0;
            if (pvalid) {
                #pragma unroll
                for (int c = 0; c < 8; c++) {
                    float mm = BETA * m1[c] + cur[c];
                    if ((sp1 >> c) & 1) mm -= th1;
                    m1[c] = mm;
                    if (mm > th1) byte |= (1u << c);
                }
                sp1 = byte;
            }
            sb[tt * PSTR + tid] = (unsigned char)byte;
        }
        if (tid < 2 && (2 * q0 + 511 + tid) < 4096) {   // halo positions
            unsigned hsp = halo_sp[tid];
            #pragma unroll
            for (int tt = 0; tt < TCH; tt++) {
                unsigned byte = 0;
                #pragma unroll
                for (int c = 0; c < 8; c++) {
                    float mm = BETA * halo_m[tid][c] + halo_cur[tid][c];
                    if ((hsp >> c) & 1) mm -= th1;
                    halo_m[tid][c] = mm;
                    if (mm > th1) byte |= (1u << c);
                }
                hsp = byte;
                sb[tt * PSTR + 512 + tid] = (unsigned char)byte;
            }
            halo_sp[tid] = hsp;
        } else if (tid < 2) {
            #pragma unroll
            for (int tt = 0; tt < TCH; tt++) sb[tt * PSTR + 512 + tid] = 0;
        }
        __syncthreads();

        // -- consume: conv2(LUT) + pool + LIF2 + FC partial
        #pragma unroll 2
        for (int tt = 0; tt < TCH; tt++) {
            const unsigned char* row = sb + tt * PSTR;
            const unsigned w0 = *reinterpret_cast<const unsigned*>(row + wbase);
            const unsigned w1w = *reinterpret_cast<const unsigned*>(row + wbase + 4);
            const unsigned sword = __funnelshift_r(w0, w1w, fsh);
            const int x0o = (int)(sword & 255u) << 5;          // float offsets
            const int x1o = (int)((sword >> 8) & 255u) << 5;
            const int x2o = (int)((sword >> 16) & 255u) << 5;
            const int x3o = (int)(sword >> 24) << 5;

            const float4 A0 = *reinterpret_cast<const float4*>(lutT + x0o);
            const float4 A1 = *reinterpret_cast<const float4*>(lutT + 8192 + x1o);
            const float4 A2 = *reinterpret_cast<const float4*>(lutT + 16384 + x2o);
            const float4 B0 = *reinterpret_cast<const float4*>(lutT + x1o);
            const float4 B1 = *reinterpret_cast<const float4*>(lutT + 8192 + x2o);
            const float4 B2 = *reinterpret_cast<const float4*>(lutT + 16384 + x3o);

            const float4 cv = max4(add4(add4(A0, A1), A2), add4(add4(B0, B1), B2));
            const float cur2[4] = {cv.x, cv.y, cv.z, cv.w};

            unsigned nib = 0;
            #pragma unroll
            for (int j = 0; j < 4; j++) {
                float mm = m2[j];
                const bool r = mm > th2;          // reset from carry-in mem
                mm = BETA * mm + cur2[j];
                if (r) mm -= th2;
                m2[j] = mm;
                if (mm > th2) nib |= (1u << j);
            }
            const unsigned own  = nib << (4 * h);
            const unsigned full = own | __shfl_xor_sync(0xffffffffu, own, 1);

            float pacc = 0.f;
            #pragma unroll
            for (int co = 0; co < 8; co++)
                if ((full >> co) & 1) pacc += fw[co];

            // truncated xor-butterfly: each 16-lane half reduced per parity
            pacc += __shfl_xor_sync(0xffffffffu, pacc, 2);
            pacc += __shfl_xor_sync(0xffffffffu, pacc, 4);
            pacc += __shfl_xor_sync(0xffffffffu, pacc, 8);

            if ((lane & 15) < 2)
                psum[ch * TCH + tt][wrp][lane >> 4][lane & 1] = pacc;
        }
        __syncthreads();
    }

    // ---- Epilogue: reduce psum over 16 warps x 2 half-warp groups
    if (tid < 64) {
        const int t = tid >> 1, o = tid & 1;
        float s = 0.f;
        #pragma unroll
        for (int w = 0; w < 16; w++)
            s += psum[t][w][0][o] + psum[t][w][1][o];
        g_partial[((b * NTILE + tile) * NT + t) * 2 + o] = s;
    }
}

__global__ __launch_bounds__(64) void snn_final(
    const float* __restrict__ fcb,
    const float* __restrict__ thop,
    float* __restrict__ out)
{
    __shared__ float sm[NT][2];
    const int b = blockIdx.x;
    const int tid = threadIdx.x;

    {
        const int t = tid >> 1, o = tid & 1;
        float s = 0.f;
        #pragma unroll
        for (int tile = 0; tile < NTILE; tile++)
            s += g_partial[((b * NTILE + tile) * NT + t) * 2 + o];
        sm[t][o] = s;
    }
    __syncthreads();

    if (tid < 2) {
        const int o = tid;
        const float tho = *thop;
        const float fb = fcb[o];
        float mo = 0.f;
        for (int t = 0; t < NT; t++) {
            const float c = sm[t][o] + fb;
            const bool r = mo > tho;
            mo = BETA * mo + c;
            if (r) mo -= tho;
            const int base = (t * 256 + b) * 2 + o;
            out[base] = (mo > tho) ? 1.f : 0.f;   // spk_rec
            out[16384 + base] = mo;               // mem_rec
        }
    }
}

extern "C" void kernel_launch(void* const* d_in, const int* in_sizes, int n_in,
                              void* d_out, int out_size)
{
    const float* x    = (const float*)d_in[0];
    const float* w1   = (const float*)d_in[1];
    const float* b1   = (const float*)d_in[2];
    const float* w2   = (const float*)d_in[3];
    const float* b2   = (const float*)d_in[4];
    const float* fcw  = (const float*)d_in[5];
    const float* fcb  = (const float*)d_in[6];
    const float* th1  = (const float*)d_in[7];
    const float* th2  = (const float*)d_in[8];
    const float* tho  = (const float*)d_in[9];
    float* out = (float*)d_out;

    cudaFuncSetAttribute(snn_main, cudaFuncAttributeMaxDynamicSharedMemorySize,
                         SMEM_TOTAL);

    snn_main<<<256 * NTILE, NTHR, SMEM_TOTAL>>>(x, w1, b1, w2, b2, fcw, th1, th2);
    snn_final<<<256, 64>>>(fcb, tho, out);
}